// round 15
// baseline (speedup 1.0000x reference)
#include <cuda_runtime.h>
#include <cuda_bf16.h>
#include <cuda_fp16.h>
#include <cstdint>

// Sizes
#define W_WORDS 4096
#define LCH 32
#define D2 512
#define D4 1024
#define KDIM 1536   // 3*512

// GEMM tiling
#define GM 128
#define GN 64
#define GK 64
#define NK (KDIM / GK)            // 24
#define A_TILE (GM * GK * 2)      // 16384 B (fp16)
#define B_TILE (GN * GK * 2)      // 8192 B
#define STAGE_B (A_TILE + B_TILE) // 24576
#define NSTAGE 4
#define SMEM_DYN_GEMM (NSTAGE * STAGE_B)    // 98304
#define SMEM_DYN_BU (3 * 128 * 128 * 2)     // 98304 : 3 tables x 128 chars x 128-dim half

// ---------------- scratch ----------------
__device__ __align__(128) __half g_Th[3 * 128 * 256];        // fp16 lookup tables
__device__ __align__(128) __half g_ua[(W_WORDS + 2) * D2];   // u in fp16
__device__ __align__(128) __half g_Bh[D2 * KDIM];            // B fp16 [o][p] K-major
__device__ __align__(128) unsigned g_rkeys[D2];
__device__ __align__(128) float  g_h[D4];

// ---------------- helpers ----------------
__device__ __forceinline__ uint32_t smem_u32(const void* p) {
    uint32_t a;
    asm("{ .reg .u64 t; cvta.to.shared.u64 t, %1; cvt.u32.u64 %0, t; }" : "=r"(a) : "l"(p));
    return a;
}
__device__ __forceinline__ void ldmx4(uint32_t* r, uint32_t addr) {
    asm volatile("ldmatrix.sync.aligned.m8n8.x4.shared.b16 {%0,%1,%2,%3}, [%4];"
                 : "=r"(r[0]), "=r"(r[1]), "=r"(r[2]), "=r"(r[3]) : "r"(addr));
}
__device__ __forceinline__ void mma_f16(float* c, const uint32_t* a, uint32_t b0, uint32_t b1) {
    asm volatile("mma.sync.aligned.m16n8k16.row.col.f32.f16.f16.f32 "
                 "{%0,%1,%2,%3}, {%4,%5,%6,%7}, {%8,%9}, {%0,%1,%2,%3};"
                 : "+f"(c[0]), "+f"(c[1]), "+f"(c[2]), "+f"(c[3])
                 : "r"(a[0]), "r"(a[1]), "r"(a[2]), "r"(a[3]), "r"(b0), "r"(b1));
}
__device__ __forceinline__ void cp16(uint32_t dst, const void* src) {
    asm volatile("cp.async.cg.shared.global [%0], [%1], 16;" :: "r"(dst), "l"(src));
}
#define CP_COMMIT() asm volatile("cp.async.commit_group;" ::: "memory")
#define CP_WAIT2()  asm volatile("cp.async.wait_group 2;" ::: "memory")
__device__ __forceinline__ __half2 H2(uint32_t v) { return *(__half2*)&v; }

// ---------------- merged prep: char tables (direct from wc) + B conversion + pads ----------------
__global__ void k_prep2(const float* __restrict__ wc,
                        const float* __restrict__ ws,
                        const float* __restrict__ chr_emb) {
    int b = blockIdx.x;
    if (b < 64) {
        __shared__ float ce[2][256];
        int d = threadIdx.x;       // 256
        int c0 = b * 2;
        ce[0][d] = chr_emb[c0 * 256 + d];
        ce[1][d] = chr_emb[(c0 + 1) * 256 + d];
        __syncthreads();
        float a[2][3] = {{0.f, 0.f, 0.f}, {0.f, 0.f, 0.f}};
        const float4* row = (const float4*)(wc + (size_t)d * 768);
        #pragma unroll 8
        for (int i4 = 0; i4 < 64; i4++) {
            float4 x0 = row[3 * i4];
            float4 x1 = row[3 * i4 + 1];
            float4 x2 = row[3 * i4 + 2];
            int ib = i4 * 4;
            #pragma unroll
            for (int q = 0; q < 2; q++) {
                float e0 = ce[q][ib], e1 = ce[q][ib + 1], e2 = ce[q][ib + 2], e3 = ce[q][ib + 3];
                a[q][0] += e0 * x0.x + e1 * x0.w + e2 * x1.z + e3 * x2.y;
                a[q][1] += e0 * x0.y + e1 * x1.x + e2 * x1.w + e3 * x2.z;
                a[q][2] += e0 * x0.z + e1 * x1.y + e2 * x2.x + e3 * x2.w;
            }
        }
        #pragma unroll
        for (int q = 0; q < 2; q++) {
            g_Th[(c0 + q) * 256 + d]         = __float2half(a[q][0]);
            g_Th[32768 + (c0 + q) * 256 + d] = __float2half(a[q][1]);
            g_Th[65536 + (c0 + q) * 256 + d] = __float2half(a[q][2]);
        }
    } else if (b < 576) {
        int o = b - 64;            // 512
        for (int p = threadIdx.x; p < KDIM; p += 256) {
            int kk = p >> 9, i = p & 511;
            g_Bh[o * KDIM + p] = __float2half(ws[o * KDIM + i * 3 + kk]);
        }
        if (o == 0) { g_rkeys[threadIdx.x] = 0u; g_rkeys[threadIdx.x + 256] = 0u; }
    } else {                       // b == 576 : zero u padding rows
        uint2 z = make_uint2(0u, 0u);
        int t = threadIdx.x;
        if (t < 128) ((uint2*)g_ua)[t] = z;
        else ((uint2*)g_ua)[(size_t)(W_WORDS + 1) * 128 + (t - 128)] = z;
    }
}

// ---------------- build u v3: warp-per-word, smem table d-halves (measured good) ----------------
__global__ __launch_bounds__(256, 2) void k_build_u(const int* __restrict__ words,
                                                    const int* __restrict__ wic,
                                                    const float* __restrict__ word_emb,
                                                    const float* __restrict__ cb) {
    extern __shared__ __align__(16) char sm[];
    int half = blockIdx.y;         // 0/1 -> dims [0,128) / [128,256) of char path
    {
        uint4* dst4 = (uint4*)sm;  // 6144 uint4
        for (int i = threadIdx.x; i < 6144; i += 256) {
            int k = i >> 11;
            int rem = i & 2047;
            int c = rem >> 4;
            int j = rem & 15;
            dst4[i] = *((const uint4*)(g_Th + (size_t)k * 32768 + c * 256 + half * 128) + j);
        }
    }
    __syncthreads();

    int lane = threadIdx.x & 31, wp = threadIdx.x >> 5;   // 8 warps
    const float4* CB = (const float4*)cb;
    float4 cb4 = CB[half * 32 + lane];
    __half2 bb0 = __floats2half2_rn(cb4.x, cb4.y);
    __half2 bb1 = __floats2half2_rn(cb4.z, cb4.w);
    const uint2* sT = (const uint2*)sm;
    uint2* UA = (uint2*)g_ua;      // row = 128 uint2 (4 halves each)
    const __half2 NEG = __half2half2(__float2half(-60000.0f));

    for (int w = blockIdx.x * 8 + wp; w < W_WORDS; w += gridDim.x * 8) {
        int code = wic[w * LCH + lane];
        int wi = words[w];
        float4 ev = ((const float4*)word_emb)[(size_t)wi * 64 + half * 32 + lane];
        {
            __half2 e0 = __floats2half2_rn(ev.x, ev.y);
            __half2 e1 = __floats2half2_rn(ev.z, ev.w);
            uint2 ep;
            ep.x = *(uint32_t*)&e0; ep.y = *(uint32_t*)&e1;
            UA[(size_t)(w + 1) * 128 + half * 32 + lane] = ep;
        }
        int c = __shfl_sync(0xffffffffu, code, 0);
        uint2 t0 = sT[c * 32 + lane];
        uint2 t1 = sT[(128 + c) * 32 + lane];
        uint2 t2 = sT[(256 + c) * 32 + lane];
        __half2 accA0 = __hadd2(bb0, H2(t1.x)), accA1 = __hadd2(bb1, H2(t1.y));
        __half2 accB0 = __hadd2(bb0, H2(t0.x)), accB1 = __hadd2(bb1, H2(t0.y));
        __half2 m0 = NEG, m1 = NEG;
        (void)t2;
        #pragma unroll
        for (int s = 1; s < LCH; s++) {
            c = __shfl_sync(0xffffffffu, code, s);
            t0 = sT[c * 32 + lane];
            t1 = sT[(128 + c) * 32 + lane];
            t2 = sT[(256 + c) * 32 + lane];
            m0 = __hmax2(m0, __hadd2(accA0, H2(t2.x)));
            m1 = __hmax2(m1, __hadd2(accA1, H2(t2.y)));
            accA0 = __hadd2(accB0, H2(t1.x));
            accA1 = __hadd2(accB1, H2(t1.y));
            accB0 = __hadd2(bb0, H2(t0.x));
            accB1 = __hadd2(bb1, H2(t0.y));
        }
        m0 = __hmax2(m0, accA0);
        m1 = __hmax2(m1, accA1);
        uint2 mp;
        mp.x = *(uint32_t*)&m0; mp.y = *(uint32_t*)&m1;
        UA[(size_t)(w + 1) * 128 + 64 + half * 32 + lane] = mp;
    }
}

// ---------------- GEMM: single-product fp16, GK=64, 4-stage pipeline (proven) ----------------
__global__ __launch_bounds__(256, 2) void k_gemm_mma() {
    extern __shared__ __align__(128) char smem[];
    uint32_t sb = smem_u32(smem);
    int tid = threadIdx.x;
    int lane = tid & 31, wq = tid >> 5;
    int wm = wq & 3, wn = wq >> 2;       // 4 m-warps x 2 n-warps; warp tile 32x32
    int n0 = blockIdx.x * GN;
    int w0 = blockIdx.y * GM;

    float acc[2][4][4];
    #pragma unroll
    for (int a = 0; a < 2; a++)
        #pragma unroll
        for (int f = 0; f < 4; f++)
            #pragma unroll
            for (int r = 0; r < 4; r++) acc[a][f][r] = 0.f;

    auto issue_stage = [&](int ck, int s) {
        int p0 = ck * GK;
        int kk = p0 >> 9, i0 = p0 & 511;
        uint32_t st = sb + s * STAGE_B;
        #pragma unroll
        for (int q = 0; q < 6; q++) {
            int idx = tid + q * 256;      // 0..1535
            if (idx < 1024) {             // A tile: 128 rows x 128B
                int r = idx >> 3, c8 = idx & 7;
                uint32_t dst = st + r * 128 + ((c8 ^ (r & 7)) << 4);
                const __half* src = g_ua + (size_t)(w0 + kk + r) * D2 + i0 + c8 * 8;
                cp16(dst, src);
            } else {                      // B tile: 64 rows x 128B
                int j = idx - 1024;
                int r = j >> 3, c8 = j & 7;
                uint32_t dst = st + A_TILE + r * 128 + ((c8 ^ (r & 7)) << 4);
                const __half* src = g_Bh + (size_t)(n0 + r) * KDIM + p0 + c8 * 8;
                cp16(dst, src);
            }
        }
        CP_COMMIT();
    };

    issue_stage(0, 0);
    issue_stage(1, 1);
    issue_stage(2, 2);

    for (int ck = 0; ck < NK; ck++) {
        CP_WAIT2();
        __syncthreads();
        if (ck + 3 < NK) issue_stage(ck + 3, (ck + 3) % NSTAGE);
        else CP_COMMIT();

        uint32_t st = sb + (ck % NSTAGE) * STAGE_B;
        uint32_t aA = st, bH = st + A_TILE;
        #pragma unroll
        for (int ks = 0; ks < 4; ks++) {
            uint32_t ah[2][4];
            #pragma unroll
            for (int mf = 0; mf < 2; mf++) {
                int row = wm * 32 + mf * 16 + (lane & 7) + ((lane >> 3) & 1) * 8;
                int c = 2 * ks + (lane >> 4);
                uint32_t off = (uint32_t)(row * 128) + (uint32_t)((c ^ (row & 7)) << 4);
                ldmx4(ah[mf], aA + off);
            }
            #pragma unroll
            for (int bq = 0; bq < 2; bq++) {
                int row = wn * 32 + bq * 16 + (lane & 7) + ((lane >> 3) & 1) * 8;
                int c = 2 * ks + (lane >> 4);
                uint32_t off = (uint32_t)(row * 128) + (uint32_t)((c ^ (row & 7)) << 4);
                uint32_t bh[4];
                ldmx4(bh, bH + off);
                #pragma unroll
                for (int mf = 0; mf < 2; mf++) {
                    mma_f16(acc[mf][2 * bq],     ah[mf], bh[0], bh[2]);
                    mma_f16(acc[mf][2 * bq + 1], ah[mf], bh[1], bh[3]);
                }
            }
        }
    }

    // epilogue: column max over tile's 128 rows
    __syncthreads();
    float* red = (float*)smem;   // [4 wm][64 cols]
    #pragma unroll
    for (int f = 0; f < 4; f++) {
        float t0 = -1e30f, t1 = -1e30f;
        #pragma unroll
        for (int mf = 0; mf < 2; mf++) {
            t0 = fmaxf(t0, fmaxf(acc[mf][f][0], acc[mf][f][2]));
            t1 = fmaxf(t1, fmaxf(acc[mf][f][1], acc[mf][f][3]));
        }
        #pragma unroll
        for (int off = 4; off < 32; off <<= 1) {
            t0 = fmaxf(t0, __shfl_xor_sync(0xffffffffu, t0, off));
            t1 = fmaxf(t1, __shfl_xor_sync(0xffffffffu, t1, off));
        }
        if (lane < 4) {
            red[wm * 64 + wn * 32 + f * 8 + 2 * lane]     = t0;
            red[wm * 64 + wn * 32 + f * 8 + 2 * lane + 1] = t1;
        }
    }
    __syncthreads();
    if (tid < 64) {
        float m = red[tid];
        #pragma unroll
        for (int q = 1; q < 4; q++) m = fmaxf(m, red[q * 64 + tid]);
        unsigned u = __float_as_uint(m);
        unsigned key = (u & 0x80000000u) ? ~u : (u | 0x80000000u);
        atomicMax(&g_rkeys[n0 + tid], key);
    }
}

// ---------------- head: warp-per-output, float4 loads (proven 5.9us) ----------------
__global__ __launch_bounds__(256) void k_h(const float* __restrict__ sb,
                                           const float* __restrict__ w1,
                                           const float* __restrict__ b1) {
    __shared__ float rs[D2];
    int tid = threadIdx.x;         // 256 = 8 warps
    int lane = tid & 31, wp = tid >> 5;
    for (int j = tid; j < D2; j += 256) {
        unsigned key = g_rkeys[j];
        unsigned u = (key & 0x80000000u) ? (key & 0x7FFFFFFFu) : ~key;
        rs[j] = __uint_as_float(u) + sb[j];
    }
    __syncthreads();
    int o = blockIdx.x * 8 + wp;   // 128 blocks x 8 warps -> 1024 outputs
    const float4* W = (const float4*)(w1 + (size_t)o * D2);
    float4 v0 = W[lane];
    float4 v1 = W[lane + 32];
    float4 v2 = W[lane + 64];
    float4 v3 = W[lane + 96];
    const float4* R = (const float4*)rs;
    float4 r0 = R[lane];
    float4 r1 = R[lane + 32];
    float4 r2 = R[lane + 64];
    float4 r3 = R[lane + 96];
    float accv = v0.x * r0.x + v0.y * r0.y + v0.z * r0.z + v0.w * r0.w
               + v1.x * r1.x + v1.y * r1.y + v1.z * r1.z + v1.w * r1.w
               + v2.x * r2.x + v2.y * r2.y + v2.z * r2.z + v2.w * r2.w
               + v3.x * r3.x + v3.y * r3.y + v3.z * r3.z + v3.w * r3.w;
    #pragma unroll
    for (int off = 16; off; off >>= 1) accv += __shfl_down_sync(0xffffffffu, accv, off);
    if (lane == 0) g_h[o] = tanhf(accv + b1[o]);
}

__global__ void k_out(const float* __restrict__ w2,
                      const float* __restrict__ b2,
                      float* __restrict__ out) {
    int j = threadIdx.x >> 5, lane = threadIdx.x & 31;
    float accv = 0.f;
    for (int l = lane; l < D4; l += 32) accv += g_h[l] * w2[j * D4 + l];
    #pragma unroll
    for (int off = 16; off; off >>= 1) accv += __shfl_down_sync(0xffffffffu, accv, off);
    if (lane == 0) out[j] = accv + b2[j];
}

extern "C" void kernel_launch(void* const* d_in, const int* in_sizes, int n_in,
                              void* d_out, int out_size) {
    const int*   words       = (const int*)d_in[0];
    const int*   wic         = (const int*)d_in[1];
    const float* word_emb    = (const float*)d_in[2];
    const float* chr_emb     = (const float*)d_in[3];
    const float* conv_chr_w  = (const float*)d_in[4];
    const float* conv_chr_b  = (const float*)d_in[5];
    const float* conv_sent_w = (const float*)d_in[6];
    const float* conv_sent_b = (const float*)d_in[7];
    const float* w1          = (const float*)d_in[8];
    const float* b1          = (const float*)d_in[9];
    const float* w2          = (const float*)d_in[10];
    const float* b2          = (const float*)d_in[11];
    float* out = (float*)d_out;

    cudaFuncSetAttribute(k_gemm_mma, cudaFuncAttributeMaxDynamicSharedMemorySize, SMEM_DYN_GEMM);
    cudaFuncSetAttribute(k_build_u, cudaFuncAttributeMaxDynamicSharedMemorySize, SMEM_DYN_BU);

    k_prep2<<<577, 256>>>(conv_chr_w, conv_sent_w, chr_emb);
    dim3 gbu(148, 2);
    k_build_u<<<gbu, 256, SMEM_DYN_BU>>>(words, wic, word_emb, conv_chr_b);
    dim3 g3(D2 / GN, W_WORDS / GM);     // 8 x 32 = 256 CTAs
    k_gemm_mma<<<g3, 256, SMEM_DYN_GEMM>>>();
    k_h<<<128, 256>>>(conv_sent_b, w1, b1);
    k_out<<<1, 64>>>(w2, b2, out);
}

// round 16
// speedup vs baseline: 1.0706x; 1.0706x over previous
#include <cuda_runtime.h>
#include <cuda_bf16.h>
#include <cuda_fp16.h>
#include <cstdint>

// Sizes
#define W_WORDS 4096
#define LCH 32
#define D2 512
#define D4 1024
#define KDIM 1536   // 3*512

// GEMM tiling
#define GM 128
#define GN 64
#define GK 64
#define NK (KDIM / GK)            // 24
#define A_TILE (GM * GK * 2)      // 16384 B (fp16)
#define B_TILE (GN * GK * 2)      // 8192 B
#define STAGE_B (A_TILE + B_TILE) // 24576
#define NSTAGE 4
#define SMEM_DYN_GEMM (NSTAGE * STAGE_B)    // 98304

// ---------------- scratch ----------------
__device__ __align__(128) __half g_Th[3 * 128 * 256];        // fp16 lookup tables
__device__ __align__(128) __half g_ua[(W_WORDS + 2) * D2];   // u in fp16
__device__ __align__(128) __half g_Bh[D2 * KDIM];            // B fp16 [o][p] K-major
__device__ __align__(128) unsigned g_rkeys[D2];
__device__ __align__(128) float  g_h[D4];

// ---------------- helpers ----------------
__device__ __forceinline__ uint32_t smem_u32(const void* p) {
    uint32_t a;
    asm("{ .reg .u64 t; cvta.to.shared.u64 t, %1; cvt.u32.u64 %0, t; }" : "=r"(a) : "l"(p));
    return a;
}
__device__ __forceinline__ void ldmx4(uint32_t* r, uint32_t addr) {
    asm volatile("ldmatrix.sync.aligned.m8n8.x4.shared.b16 {%0,%1,%2,%3}, [%4];"
                 : "=r"(r[0]), "=r"(r[1]), "=r"(r[2]), "=r"(r[3]) : "r"(addr));
}
__device__ __forceinline__ void mma_f16(float* c, const uint32_t* a, uint32_t b0, uint32_t b1) {
    asm volatile("mma.sync.aligned.m16n8k16.row.col.f32.f16.f16.f32 "
                 "{%0,%1,%2,%3}, {%4,%5,%6,%7}, {%8,%9}, {%0,%1,%2,%3};"
                 : "+f"(c[0]), "+f"(c[1]), "+f"(c[2]), "+f"(c[3])
                 : "r"(a[0]), "r"(a[1]), "r"(a[2]), "r"(a[3]), "r"(b0), "r"(b1));
}
__device__ __forceinline__ void cp16(uint32_t dst, const void* src) {
    asm volatile("cp.async.cg.shared.global [%0], [%1], 16;" :: "r"(dst), "l"(src));
}
#define CP_COMMIT() asm volatile("cp.async.commit_group;" ::: "memory")
#define CP_WAIT2()  asm volatile("cp.async.wait_group 2;" ::: "memory")
#define GDC_LAUNCH() asm volatile("griddepcontrol.launch_dependents;")
#define GDC_WAIT()   asm volatile("griddepcontrol.wait;" ::: "memory")

// ---------------- merged prep: char tables (direct from wc) + B conversion ----------------
__global__ void k_prep2(const float* __restrict__ wc,
                        const float* __restrict__ ws,
                        const float* __restrict__ chr_emb) {
    int b = blockIdx.x;
    if (b < 64) {
        __shared__ float ce[2][256];
        int d = threadIdx.x;       // 256
        int c0 = b * 2;
        ce[0][d] = chr_emb[c0 * 256 + d];
        ce[1][d] = chr_emb[(c0 + 1) * 256 + d];
        __syncthreads();
        float a[2][3] = {{0.f, 0.f, 0.f}, {0.f, 0.f, 0.f}};
        const float4* row = (const float4*)(wc + (size_t)d * 768);
        #pragma unroll 8
        for (int i4 = 0; i4 < 64; i4++) {
            float4 x0 = row[3 * i4];
            float4 x1 = row[3 * i4 + 1];
            float4 x2 = row[3 * i4 + 2];
            int ib = i4 * 4;
            #pragma unroll
            for (int q = 0; q < 2; q++) {
                float e0 = ce[q][ib], e1 = ce[q][ib + 1], e2 = ce[q][ib + 2], e3 = ce[q][ib + 3];
                a[q][0] += e0 * x0.x + e1 * x0.w + e2 * x1.z + e3 * x2.y;
                a[q][1] += e0 * x0.y + e1 * x1.x + e2 * x1.w + e3 * x2.z;
                a[q][2] += e0 * x0.z + e1 * x1.y + e2 * x2.x + e3 * x2.w;
            }
        }
        #pragma unroll
        for (int q = 0; q < 2; q++) {
            g_Th[(c0 + q) * 256 + d]         = __float2half(a[q][0]);
            g_Th[32768 + (c0 + q) * 256 + d] = __float2half(a[q][1]);
            g_Th[65536 + (c0 + q) * 256 + d] = __float2half(a[q][2]);
        }
    } else {
        int o = b - 64;            // 512
        for (int p = threadIdx.x; p < KDIM; p += 256) {
            int kk = p >> 9, i = p & 511;
            g_Bh[o * KDIM + p] = __float2half(ws[o * KDIM + i * 3 + kk]);
        }
        if (o == 0) { g_rkeys[threadIdx.x] = 0u; g_rkeys[threadIdx.x + 256] = 0u; }
    }
    __syncthreads();
    GDC_LAUNCH();
}

// ---------------- build u: streaming (proven), PDL prologue = emb gather ----------------
__global__ void k_build_u(const int* __restrict__ words,
                          const int* __restrict__ wic,
                          const float* __restrict__ word_emb,
                          const float* __restrict__ cb) {
    int w = blockIdx.x;            // 4096
    int t = threadIdx.x;           // 128
    __shared__ int codes[LCH];
    if (t < LCH) codes[t] = wic[w * LCH + t];

    // --- independent of prep2: word-emb gather + pads ---
    const float2* WE = (const float2*)word_emb;
    float2 wv = WE[(size_t)words[w] * 128 + t];
    __half2* UA = (__half2*)g_ua;  // row = 256 half2
    UA[(w + 1) * 256 + t] = __floats2half2_rn(wv.x, wv.y);
    __half2 z = __floats2half2_rn(0.f, 0.f);
    if (w == 0) { UA[t] = z; UA[128 + t] = z; }
    if (w == W_WORDS - 1) {
        size_t r = (size_t)(W_WORDS + 1) * 256;
        UA[r + t] = z; UA[r + 128 + t] = z;
    }
    float2 cbv = ((const float2*)cb)[t];
    __half2 bb = __floats2half2_rn(cbv.x, cbv.y);

    GDC_WAIT();                    // tables ready (prep2)
    __syncthreads();               // codes ready

    const __half2* T0 = (const __half2*)g_Th;            // each table = 16384 half2
    const __half2* T1 = T0 + 16384;
    const __half2* T2 = T0 + 32768;

    int c = codes[0];
    __half2 a0 = T0[c * 128 + t];
    __half2 a1 = T1[c * 128 + t];
    __half2 a2 = T2[c * 128 + t];
    __half2 accA = __hadd2(bb, a1);
    __half2 accB = __hadd2(bb, a0);
    __half2 m = __half2half2(__float2half(-60000.0f));
    (void)a2;
    #pragma unroll
    for (int s = 1; s < LCH; s++) {
        c = codes[s];
        a0 = T0[c * 128 + t];
        a1 = T1[c * 128 + t];
        a2 = T2[c * 128 + t];
        m = __hmax2(m, __hadd2(accA, a2));
        accA = __hadd2(accB, a1);
        accB = __hadd2(bb, a0);
    }
    m = __hmax2(m, accA);
    UA[(w + 1) * 256 + 128 + t] = m;
    __syncthreads();
    GDC_LAUNCH();
}

// ---------------- GEMM: single-product fp16, GK=64, 4-stage (proven 26.5us) + PDL ----------------
__global__ __launch_bounds__(256, 2) void k_gemm_mma() {
    extern __shared__ __align__(128) char smem[];
    uint32_t sb = smem_u32(smem);
    int tid = threadIdx.x;
    int lane = tid & 31, wq = tid >> 5;
    int wm = wq & 3, wn = wq >> 2;       // 4 m-warps x 2 n-warps; warp tile 32x32
    int n0 = blockIdx.x * GN;
    int w0 = blockIdx.y * GM;

    // prologue: warm L2 with first 3 B stages (g_Bh ready since prep2)
    if (tid < 192) {
        const __half* pf = g_Bh + (size_t)(n0 + (tid & 63)) * KDIM + (tid >> 6) * 64;
        asm volatile("prefetch.global.L2 [%0];" :: "l"(pf));
    }
    GDC_WAIT();                    // g_ua ready (build_u)

    float acc[2][4][4];
    #pragma unroll
    for (int a = 0; a < 2; a++)
        #pragma unroll
        for (int f = 0; f < 4; f++)
            #pragma unroll
            for (int r = 0; r < 4; r++) acc[a][f][r] = 0.f;

    auto issue_stage = [&](int ck, int s) {
        int p0 = ck * GK;
        int kk = p0 >> 9, i0 = p0 & 511;
        uint32_t st = sb + s * STAGE_B;
        #pragma unroll
        for (int q = 0; q < 6; q++) {
            int idx = tid + q * 256;      // 0..1535
            if (idx < 1024) {             // A tile: 128 rows x 128B
                int r = idx >> 3, c8 = idx & 7;
                uint32_t dst = st + r * 128 + ((c8 ^ (r & 7)) << 4);
                const __half* src = g_ua + (size_t)(w0 + kk + r) * D2 + i0 + c8 * 8;
                cp16(dst, src);
            } else {                      // B tile: 64 rows x 128B
                int j = idx - 1024;
                int r = j >> 3, c8 = j & 7;
                uint32_t dst = st + A_TILE + r * 128 + ((c8 ^ (r & 7)) << 4);
                const __half* src = g_Bh + (size_t)(n0 + r) * KDIM + p0 + c8 * 8;
                cp16(dst, src);
            }
        }
        CP_COMMIT();
    };

    issue_stage(0, 0);
    issue_stage(1, 1);
    issue_stage(2, 2);

    for (int ck = 0; ck < NK; ck++) {
        CP_WAIT2();
        __syncthreads();
        if (ck + 3 < NK) issue_stage(ck + 3, (ck + 3) % NSTAGE);
        else CP_COMMIT();

        uint32_t st = sb + (ck % NSTAGE) * STAGE_B;
        uint32_t aA = st, bH = st + A_TILE;
        #pragma unroll
        for (int ks = 0; ks < 4; ks++) {
            uint32_t ah[2][4];
            #pragma unroll
            for (int mf = 0; mf < 2; mf++) {
                int row = wm * 32 + mf * 16 + (lane & 7) + ((lane >> 3) & 1) * 8;
                int c = 2 * ks + (lane >> 4);
                uint32_t off = (uint32_t)(row * 128) + (uint32_t)((c ^ (row & 7)) << 4);
                ldmx4(ah[mf], aA + off);
            }
            #pragma unroll
            for (int bq = 0; bq < 2; bq++) {
                int row = wn * 32 + bq * 16 + (lane & 7) + ((lane >> 3) & 1) * 8;
                int c = 2 * ks + (lane >> 4);
                uint32_t off = (uint32_t)(row * 128) + (uint32_t)((c ^ (row & 7)) << 4);
                uint32_t bh[4];
                ldmx4(bh, bH + off);
                #pragma unroll
                for (int mf = 0; mf < 2; mf++) {
                    mma_f16(acc[mf][2 * bq],     ah[mf], bh[0], bh[2]);
                    mma_f16(acc[mf][2 * bq + 1], ah[mf], bh[1], bh[3]);
                }
            }
        }
    }

    // epilogue: column max over tile's 128 rows
    __syncthreads();
    float* red = (float*)smem;   // [4 wm][64 cols]
    #pragma unroll
    for (int f = 0; f < 4; f++) {
        float t0 = -1e30f, t1 = -1e30f;
        #pragma unroll
        for (int mf = 0; mf < 2; mf++) {
            t0 = fmaxf(t0, fmaxf(acc[mf][f][0], acc[mf][f][2]));
            t1 = fmaxf(t1, fmaxf(acc[mf][f][1], acc[mf][f][3]));
        }
        #pragma unroll
        for (int off = 4; off < 32; off <<= 1) {
            t0 = fmaxf(t0, __shfl_xor_sync(0xffffffffu, t0, off));
            t1 = fmaxf(t1, __shfl_xor_sync(0xffffffffu, t1, off));
        }
        if (lane < 4) {
            red[wm * 64 + wn * 32 + f * 8 + 2 * lane]     = t0;
            red[wm * 64 + wn * 32 + f * 8 + 2 * lane + 1] = t1;
        }
    }
    __syncthreads();
    if (tid < 64) {
        float m = red[tid];
        #pragma unroll
        for (int q = 1; q < 4; q++) m = fmaxf(m, red[q * 64 + tid]);
        unsigned u = __float_as_uint(m);
        unsigned key = (u & 0x80000000u) ? ~u : (u | 0x80000000u);
        atomicMax(&g_rkeys[n0 + tid], key);
    }
    __syncthreads();
    GDC_LAUNCH();
}

// ---------------- head: warp-per-output, W1 loads before PDL wait ----------------
__global__ __launch_bounds__(256) void k_h(const float* __restrict__ sb,
                                           const float* __restrict__ w1,
                                           const float* __restrict__ b1) {
    __shared__ float rs[D2];
    int tid = threadIdx.x;         // 256 = 8 warps
    int lane = tid & 31, wp = tid >> 5;
    int o = blockIdx.x * 8 + wp;   // 128 blocks x 8 warps -> 1024 outputs
    const float4* W = (const float4*)(w1 + (size_t)o * D2);
    float4 v0 = W[lane];
    float4 v1 = W[lane + 32];
    float4 v2 = W[lane + 64];
    float4 v3 = W[lane + 96];
    float bo = b1[o];
    GDC_WAIT();                    // rkeys ready (gemm)
    for (int j = tid; j < D2; j += 256) {
        unsigned key = g_rkeys[j];
        unsigned u = (key & 0x80000000u) ? (key & 0x7FFFFFFFu) : ~key;
        rs[j] = __uint_as_float(u) + sb[j];
    }
    __syncthreads();
    const float4* R = (const float4*)rs;
    float4 r0 = R[lane];
    float4 r1 = R[lane + 32];
    float4 r2 = R[lane + 64];
    float4 r3 = R[lane + 96];
    float accv = v0.x * r0.x + v0.y * r0.y + v0.z * r0.z + v0.w * r0.w
               + v1.x * r1.x + v1.y * r1.y + v1.z * r1.z + v1.w * r1.w
               + v2.x * r2.x + v2.y * r2.y + v2.z * r2.z + v2.w * r2.w
               + v3.x * r3.x + v3.y * r3.y + v3.z * r3.z + v3.w * r3.w;
    #pragma unroll
    for (int off = 16; off; off >>= 1) accv += __shfl_down_sync(0xffffffffu, accv, off);
    if (lane == 0) g_h[o] = tanhf(accv + bo);
    __syncthreads();
    GDC_LAUNCH();
}

__global__ void k_out(const float* __restrict__ w2,
                      const float* __restrict__ b2,
                      float* __restrict__ out) {
    int j = threadIdx.x >> 5, lane = threadIdx.x & 31;
    const float4* W2 = (const float4*)(w2 + (size_t)j * D4);
    float4 wv[8];
    #pragma unroll
    for (int q = 0; q < 8; q++) wv[q] = W2[lane + 32 * q];
    float bj = b2[j];
    GDC_WAIT();                    // g_h ready (k_h)
    const float4* H = (const float4*)g_h;
    float accv = 0.f;
    #pragma unroll
    for (int q = 0; q < 8; q++) {
        float4 h = H[lane + 32 * q];
        accv += wv[q].x * h.x + wv[q].y * h.y + wv[q].z * h.z + wv[q].w * h.w;
    }
    #pragma unroll
    for (int off = 16; off; off >>= 1) accv += __shfl_down_sync(0xffffffffu, accv, off);
    if (lane == 0) out[j] = accv + bj;
}

extern "C" void kernel_launch(void* const* d_in, const int* in_sizes, int n_in,
                              void* d_out, int out_size) {
    const int*   words       = (const int*)d_in[0];
    const int*   wic         = (const int*)d_in[1];
    const float* word_emb    = (const float*)d_in[2];
    const float* chr_emb     = (const float*)d_in[3];
    const float* conv_chr_w  = (const float*)d_in[4];
    const float* conv_chr_b  = (const float*)d_in[5];
    const float* conv_sent_w = (const float*)d_in[6];
    const float* conv_sent_b = (const float*)d_in[7];
    const float* w1          = (const float*)d_in[8];
    const float* b1          = (const float*)d_in[9];
    const float* w2          = (const float*)d_in[10];
    const float* b2          = (const float*)d_in[11];
    float* out = (float*)d_out;

    cudaFuncSetAttribute(k_gemm_mma, cudaFuncAttributeMaxDynamicSharedMemorySize, SMEM_DYN_GEMM);

    // first launch: plain
    k_prep2<<<576, 256>>>(conv_chr_w, conv_sent_w, chr_emb);

    cudaLaunchAttribute at{};
    at.id = cudaLaunchAttributeProgrammaticStreamSerialization;
    at.val.programmaticStreamSerializationAllowed = 1;

    {   // build_u (PDL after prep2)
        cudaLaunchConfig_t cfg{};
        cfg.gridDim = dim3(W_WORDS, 1, 1);
        cfg.blockDim = dim3(128, 1, 1);
        cfg.attrs = &at; cfg.numAttrs = 1;
        cudaLaunchKernelEx(&cfg, k_build_u, words, wic, word_emb, conv_chr_b);
    }
    {   // gemm (PDL after build_u)
        cudaLaunchConfig_t cfg{};
        cfg.gridDim = dim3(D2 / GN, W_WORDS / GM, 1);
        cfg.blockDim = dim3(256, 1, 1);
        cfg.dynamicSmemBytes = SMEM_DYN_GEMM;
        cfg.attrs = &at; cfg.numAttrs = 1;
        cudaLaunchKernelEx(&cfg, k_gemm_mma);
    }
    {   // k_h (PDL after gemm)
        cudaLaunchConfig_t cfg{};
        cfg.gridDim = dim3(128, 1, 1);
        cfg.blockDim = dim3(256, 1, 1);
        cfg.attrs = &at; cfg.numAttrs = 1;
        cudaLaunchKernelEx(&cfg, k_h, conv_sent_b, w1, b1);
    }
    {   // k_out (PDL after k_h)
        cudaLaunchConfig_t cfg{};
        cfg.gridDim = dim3(1, 1, 1);
        cfg.blockDim = dim3(64, 1, 1);
        cfg.attrs = &at; cfg.numAttrs = 1;
        cudaLaunchKernelEx(&cfg, k_out, w2, b2, out);
    }
}